// round 11
// baseline (speedup 1.0000x reference)
#include <cuda_runtime.h>
#include <cstddef>

// x: (8, 16, 3, 256, 256) fp32; out: (128, 2, 256, 256) fp32
// out[bl, ch, hw] = plane(bl*3) - plane((bl-1)*3), zero when bl%16==0; ch0==ch1.
//
// R10 config (coalesced, __ldg + __stcs streaming stores, 512-thread blocks)
// + ILP-2 in the warp-interleaved (coalesced) direction: each thread handles
// float4 chunks j and j+HWV of its plane. 4 front-batched loads / 4 stores
// per thread, 2048 blocks total.

static constexpr int HW4 = 16384;         // 256*256/4 float4 per plane
static constexpr int HWV = HW4 / 2;       // 8192 thread-slots per plane
static constexpr int BL  = 128;           // 8*16
static constexpr int TOTALT = BL * HWV;   // 1,048,576 threads

__global__ __launch_bounds__(512) void dummyflow_diff_kernel(
    const float4* __restrict__ x, float4* __restrict__ out)
{
    int idx = blockIdx.x * blockDim.x + threadIdx.x;
    if (idx >= TOTALT) return;

    int bl = idx >> 13;          // idx / HWV
    int j  = idx & (HWV - 1);    // within-plane slot (coalesced)
    int l  = bl & 15;

    size_t obase = (size_t)(bl * 2) * HW4 + j;

    if (l == 0) {
        float4 z = make_float4(0.f, 0.f, 0.f, 0.f);
        __stcs(&out[obase],             z);
        __stcs(&out[obase + HWV],       z);
        __stcs(&out[obase + HW4],       z);
        __stcs(&out[obase + HW4 + HWV], z);
        return;
    }

    size_t cur  = (size_t)(bl * 3)       * HW4 + j;
    size_t prev = (size_t)((bl - 1) * 3) * HW4 + j;

    // 4 independent fully-coalesced LDG.128
    float4 a0 = __ldg(&x[cur]);
    float4 a1 = __ldg(&x[cur + HWV]);
    float4 p0 = __ldg(&x[prev]);
    float4 p1 = __ldg(&x[prev + HWV]);

    float4 v0 = make_float4(a0.x - p0.x, a0.y - p0.y, a0.z - p0.z, a0.w - p0.w);
    float4 v1 = make_float4(a1.x - p1.x, a1.y - p1.y, a1.z - p1.z, a1.w - p1.w);

    __stcs(&out[obase],             v0);   // ch0, chunk 0
    __stcs(&out[obase + HWV],       v1);   // ch0, chunk 1
    __stcs(&out[obase + HW4],       v0);   // ch1, chunk 0
    __stcs(&out[obase + HW4 + HWV], v1);   // ch1, chunk 1
}

extern "C" void kernel_launch(void* const* d_in, const int* in_sizes, int n_in,
                              void* d_out, int out_size)
{
    const float4* x = (const float4*)d_in[0];
    float4* out = (float4*)d_out;

    int threads = 512;
    int blocks = TOTALT / threads;   // 2048
    dummyflow_diff_kernel<<<blocks, threads>>>(x, out);
}